// round 4
// baseline (speedup 1.0000x reference)
#include <cuda_runtime.h>
#include <cstdint>
#include <cstddef>

// Problem constants (fixed by the reference)
#define E_N   1000000
#define V_N   200000
#define D_N   128
#define FE_N  16
#define DIN   145          // D + Fe + 1
#define DINP  160          // padded K for GEMM1
#define HM    256
#define HAG   256
#define HA    256

// Scratch: aggregation buffer [V, HAG] (device global — allocation-free rule)
__device__ float g_agg[(size_t)V_N * HAG];

// ---------------- packed f32x2 helpers (Blackwell FFMA2 path) ----------------
__device__ __forceinline__ unsigned long long pack2(float lo, float hi) {
    unsigned long long r;
    asm("mov.b64 %0, {%1, %2};" : "=l"(r)
        : "r"(__float_as_uint(lo)), "r"(__float_as_uint(hi)));
    return r;
}
__device__ __forceinline__ void unpack2(unsigned long long v, float& lo, float& hi) {
    unsigned int a, b;
    asm("mov.b64 {%0, %1}, %2;" : "=r"(a), "=r"(b) : "l"(v));
    lo = __uint_as_float(a);
    hi = __uint_as_float(b);
}
__device__ __forceinline__ void fma2(unsigned long long& d,
                                     unsigned long long a, unsigned long long b) {
    asm("fma.rn.f32x2 %0, %1, %2, %0;" : "+l"(d) : "l"(a), "l"(b));
}

// fast log-sigmoid: min(x,0) - log(1 + exp(-|x|)); abs err ~1e-7, fine vs 1e-3 tol
__device__ __forceinline__ float lsig(float x) {
    return fminf(x, 0.0f) - __logf(1.0f + __expf(-fabsf(x)));
}

// ---------------- zero the aggregation buffer ----------------
__global__ void zero_agg_kernel() {
    size_t idx = (size_t)blockIdx.x * blockDim.x + threadIdx.x;  // one float4 each
    reinterpret_cast<float4*>(g_agg)[idx] = make_float4(0.f, 0.f, 0.f, 0.f);
}

// ---------------- shared GEMM tile: [64 rows x 256 cols], 256 threads ----------------
// Thread tile: 8 rows x 8 cols (cols paired for FFMA2). jg=tid&31 -> j0=8*jg,
// eg=tid>>5 -> e0=8*eg. ws chunk layout: ws[kk*264 + j].
template <int KTOT, int KVALID, int XSTR>
__device__ __forceinline__ void gemm_tile_256(
    const float* __restrict__ Wg, int wld,
    const float* xbuf, float* ws,
    unsigned long long acc[8][4],
    int tid, int e0, int j0)
{
#pragma unroll 1
    for (int kb = 0; kb < KTOT; kb += 16) {
        __syncthreads();   // ws free to overwrite; also covers producer of xbuf on iter 0
#pragma unroll
        for (int kk = 0; kk < 16; kk++) {
            int k = kb + kk;
            float w = 0.0f;
            if (KVALID == KTOT || k < KVALID) w = __ldg(Wg + (size_t)tid * wld + k);
            ws[kk * 264 + tid] = w;
        }
        __syncthreads();
#pragma unroll
        for (int kk = 0; kk < 16; kk++) {
            unsigned long long b2[4];
#pragma unroll
            for (int u = 0; u < 4; u++)
                b2[u] = *reinterpret_cast<const unsigned long long*>(ws + kk * 264 + j0 + 2 * u);
#pragma unroll
            for (int i = 0; i < 8; i++) {
                float a = xbuf[(e0 + i) * XSTR + kb + kk];   // warp-broadcast LDS
                unsigned long long a2 = pack2(a, a);
#pragma unroll
                for (int u = 0; u < 4; u++) fma2(acc[i][u], a2, b2[u]);
            }
        }
    }
}

// ---------------- edge kernel: X -> MLP(145,256,256) -> scatter-add ----------------
// smem (floats): xs[64][164] @0 (10496) | h1[64][260] @10496 (16640) |
//                ws[16][264] @27136 (4224) | svi[64] @31360  => 125696 bytes
#define EDGE_SMEM_FLOATS 31424
#define EDGE_SMEM_BYTES  (EDGE_SMEM_FLOATS * 4)

__global__ __launch_bounds__(256, 1) void edge_kernel(
    const float* __restrict__ vs, const float* __restrict__ ef,
    const float* __restrict__ sol, const float* __restrict__ W1m,
    const float* __restrict__ b1m, const float* __restrict__ W2m,
    const int* __restrict__ vidx, const int* __restrict__ esign)
{
    extern __shared__ float sm[];
    float* xs = sm;                 // [64][164]
    float* h1 = sm + 10496;        // [64][260]
    float* ws = sm + 27136;        // [16][264]
    int*   svi = (int*)(sm + 31360);

    const int tid = threadIdx.x;
    const int ebase = blockIdx.x * 64;

    // ---- stage X tile into smem ----
#pragma unroll
    for (int it = 0; it < 8; it++) {                 // 64 rows x 32 float4 of state
        int idx = tid + it * 256;
        int e = idx >> 5, c = idx & 31;
        float4 v = __ldg(reinterpret_cast<const float4*>(vs + (size_t)(ebase + e) * D_N) + c);
        float* row = xs + e * 164 + c * 4;
        row[0] = v.x; row[1] = v.y; row[2] = v.z; row[3] = v.w;
    }
    {                                                // 64 rows x 4 float4 of edge feature
        int e = tid >> 2, c = tid & 3;
        float4 v = __ldg(reinterpret_cast<const float4*>(ef + (size_t)(ebase + e) * FE_N) + c);
        float* row = xs + e * 164 + D_N + c * 4;
        row[0] = v.x; row[1] = v.y; row[2] = v.z; row[3] = v.w;
    }
    if (tid < 64) {                                  // signed solution + zero pad
        int e = tid;
        int vi = __ldg(vidx + ebase + e);
        svi[e] = vi;
        float sg = (float)__ldg(esign + ebase + e);
        xs[e * 164 + 144] = sg * __ldg(sol + vi);
#pragma unroll
        for (int k = DIN; k < DINP; k++) xs[e * 164 + k] = 0.0f;
    }

    const int jg = tid & 31, eg = tid >> 5;
    const int j0 = jg * 8, e0 = eg * 8;

    float bias[8];
#pragma unroll
    for (int jj = 0; jj < 8; jj++) bias[jj] = __ldg(b1m + j0 + jj);

    // ---- GEMM1: h1 = lsig(X @ W1m^T + b1m) ----
    unsigned long long acc[8][4];
#pragma unroll
    for (int i = 0; i < 8; i++)
#pragma unroll
        for (int u = 0; u < 4; u++) acc[i][u] = 0ull;

    gemm_tile_256<DINP, DIN, 164>(W1m, DIN, xs, ws, acc, tid, e0, j0);

#pragma unroll
    for (int i = 0; i < 8; i++) {
        float* hrow = h1 + (e0 + i) * 260 + j0;
#pragma unroll
        for (int u = 0; u < 4; u++) {
            float lo, hi;
            unpack2(acc[i][u], lo, hi);
            hrow[2 * u]     = lsig(lo + bias[2 * u]);
            hrow[2 * u + 1] = lsig(hi + bias[2 * u + 1]);
            acc[i][u] = 0ull;   // reset for GEMM2
        }
    }

    // ---- GEMM2: s = lsig(h1 @ W2m^T) ----
    gemm_tile_256<HM, HM, 260>(W2m, HM, h1, ws, acc, tid, e0, j0);

    // ---- epilogue: vector RED scatter into g_agg ----
#pragma unroll
    for (int i = 0; i < 8; i++) {
        float v0, v1, v2, v3, v4, v5, v6, v7;
        unpack2(acc[i][0], v0, v1);
        unpack2(acc[i][1], v2, v3);
        unpack2(acc[i][2], v4, v5);
        unpack2(acc[i][3], v6, v7);
        float4 q0 = make_float4(lsig(v0), lsig(v1), lsig(v2), lsig(v3));
        float4 q1 = make_float4(lsig(v4), lsig(v5), lsig(v6), lsig(v7));
        float* base = g_agg + (size_t)svi[e0 + i] * HAG + j0;
        atomicAdd(reinterpret_cast<float4*>(base), q0);       // sm_90+ vector red
        atomicAdd(reinterpret_cast<float4*>(base + 4), q1);
    }
}

// ---------------- variable kernel: agg -> MLP(256,256,128) -> classifier ----------------
// smem (floats): as[64][260] @0 (16640) | h1[64][260] @16640 (16640) |
//                ws[16][264] @33280 (4224) | h2[64][132] @37504 (8448) => 183808 bytes
#define VAR_SMEM_FLOATS 45952
#define VAR_SMEM_BYTES  (VAR_SMEM_FLOATS * 4)

__global__ __launch_bounds__(256, 1) void var_kernel(
    const float* __restrict__ W1a, const float* __restrict__ b1a,
    const float* __restrict__ W2a, const float* __restrict__ Wc,
    const float* __restrict__ bc, float* __restrict__ out)
{
    extern __shared__ float sm[];
    float* as_ = sm;                // [64][260]
    float* h1  = sm + 16640;       // [64][260]
    float* ws  = sm + 33280;       // [16][264]
    float* h2  = sm + 37504;       // [64][132]

    const int tid = threadIdx.x;
    const int vb = blockIdx.x * 64;

    // load agg tile: 64 x 256 = 64 x 64 float4
#pragma unroll
    for (int it = 0; it < 16; it++) {
        int idx = tid + it * 256;
        int e = idx >> 6, c = idx & 63;
        float4 v = reinterpret_cast<const float4*>(g_agg + (size_t)(vb + e) * HAG)[c];
        float* row = as_ + e * 260 + c * 4;
        row[0] = v.x; row[1] = v.y; row[2] = v.z; row[3] = v.w;
    }

    const int jg = tid & 31, eg = tid >> 5;
    const int j0 = jg * 8, e0 = eg * 8;

    float bias[8];
#pragma unroll
    for (int jj = 0; jj < 8; jj++) bias[jj] = __ldg(b1a + j0 + jj);

    // ---- GEMM1: h1 = lsig(agg @ W1a^T + b1a) ----
    unsigned long long acc[8][4];
#pragma unroll
    for (int i = 0; i < 8; i++)
#pragma unroll
        for (int u = 0; u < 4; u++) acc[i][u] = 0ull;

    gemm_tile_256<HAG, HAG, 260>(W1a, HAG, as_, ws, acc, tid, e0, j0);

#pragma unroll
    for (int i = 0; i < 8; i++) {
        float* hrow = h1 + (e0 + i) * 260 + j0;
#pragma unroll
        for (int u = 0; u < 4; u++) {
            float lo, hi;
            unpack2(acc[i][u], lo, hi);
            hrow[2 * u]     = lsig(lo + bias[2 * u]);
            hrow[2 * u + 1] = lsig(hi + bias[2 * u + 1]);
        }
    }

    // ---- GEMM2: h2 = lsig(h1 @ W2a^T)  [64 x 128] ----
    const int jg2 = tid & 15, eg2 = tid >> 4;
    const int j02 = jg2 * 8, e02 = eg2 * 4;

    unsigned long long acc2[4][4];
#pragma unroll
    for (int i = 0; i < 4; i++)
#pragma unroll
        for (int u = 0; u < 4; u++) acc2[i][u] = 0ull;

#pragma unroll 1
    for (int kb = 0; kb < HA; kb += 16) {
        __syncthreads();
        {
            int j = tid & 127;
            int kh = (tid >> 7) * 8;
#pragma unroll
            for (int q = 0; q < 8; q++)
                ws[(kh + q) * 264 + j] = __ldg(W2a + (size_t)j * HA + kb + kh + q);
        }
        __syncthreads();
#pragma unroll
        for (int kk = 0; kk < 16; kk++) {
            unsigned long long b2[4];
#pragma unroll
            for (int u = 0; u < 4; u++)
                b2[u] = *reinterpret_cast<const unsigned long long*>(ws + kk * 264 + j02 + 2 * u);
#pragma unroll
            for (int i = 0; i < 4; i++) {
                float a = h1[(e02 + i) * 260 + kb + kk];
                unsigned long long a2 = pack2(a, a);
#pragma unroll
                for (int u = 0; u < 4; u++) fma2(acc2[i][u], a2, b2[u]);
            }
        }
    }

#pragma unroll
    for (int i = 0; i < 4; i++) {
        float* hrow = h2 + (e02 + i) * 132 + j02;
#pragma unroll
        for (int u = 0; u < 4; u++) {
            float lo, hi;
            unpack2(acc2[i][u], lo, hi);
            hrow[2 * u]     = lsig(lo);
            hrow[2 * u + 1] = lsig(hi);
        }
    }
    __syncthreads();

    // ---- classifier: out = h2 @ Wc^T + bc  [64 x 2] ----
    if (tid < 128) {
        int e = tid >> 1, p = tid & 1;
        float accv = __ldg(bc + p);
        const float* w = Wc + p * D_N;
        const float* hrow = h2 + e * 132;
#pragma unroll 8
        for (int j = 0; j < D_N; j++) accv = fmaf(hrow[j], __ldg(w + j), accv);
        out[(size_t)(vb + e) * 2 + p] = accv;
    }
}

// ---------------- launch ----------------
extern "C" void kernel_launch(void* const* d_in, const int* in_sizes, int n_in,
                              void* d_out, int out_size)
{
    const float* vs   = (const float*)d_in[0];   // variable_state [E, 128]
    const float* ef   = (const float*)d_in[1];   // edge_feature   [E, 16]
    const float* sol  = (const float*)d_in[2];   // solution       [V]
    const float* W1m  = (const float*)d_in[3];   // [256, 145]
    const float* b1m  = (const float*)d_in[4];   // [256]
    const float* W2m  = (const float*)d_in[5];   // [256, 256]
    const float* W1a  = (const float*)d_in[6];   // [256, 256]
    const float* b1a  = (const float*)d_in[7];   // [256]
    const float* W2a  = (const float*)d_in[8];   // [128, 256]
    const float* Wc   = (const float*)d_in[9];   // [2, 128]
    const float* bc   = (const float*)d_in[10];  // [2]
    const int*  vidx  = (const int*)d_in[11];    // [E]
    const int*  esign = (const int*)d_in[12];    // [E]
    float* out = (float*)d_out;                  // [V, 2]

    cudaFuncSetAttribute(edge_kernel, cudaFuncAttributeMaxDynamicSharedMemorySize, EDGE_SMEM_BYTES);
    cudaFuncSetAttribute(var_kernel,  cudaFuncAttributeMaxDynamicSharedMemorySize, VAR_SMEM_BYTES);

    // g_agg has V*HAG = 51,200,000 floats = 12,800,000 float4 = 50000 blocks x 256
    zero_agg_kernel<<<50000, 256>>>();
    edge_kernel<<<E_N / 64, 256, EDGE_SMEM_BYTES>>>(vs, ef, sol, W1m, b1m, W2m, vidx, esign);
    var_kernel<<<V_N / 64, 256, VAR_SMEM_BYTES>>>(W1a, b1a, W2a, Wc, bc, out);
}

// round 6
// speedup vs baseline: 3.1263x; 3.1263x over previous
#include <cuda_runtime.h>
#include <cuda_bf16.h>
#include <cstdint>
#include <cstddef>

#define E_N 1000000
#define V_N 200000

// ---------------- device scratch (allocation-free rule) ----------------
__device__ __align__(128) float g_agg[(size_t)V_N * 256];
// n-major bf16 weights, hi|lo concatenated along k: W'[n][2K]
__device__ __align__(128) __nv_bfloat16 g_w1m_p[256 * 320];   // K=160 (145 valid)
__device__ __align__(128) __nv_bfloat16 g_w2m_p[256 * 512];   // K=256
__device__ __align__(128) __nv_bfloat16 g_w1a_p[256 * 512];   // K=256
__device__ __align__(128) __nv_bfloat16 g_w2a_p[128 * 512];   // K=256, N=128

// ---------------- smem layout (bytes) ----------------
// A/h1/h2 region: 128 x 520 bf16 = 133120 (also reused as 128 x 260 fp32)
#define B_OFF    133120        // 2 x 20480 B-chunk buffers ([256][40] bf16)
#define BIAS_OFF 174080        // 256 floats
#define AUX_OFF  175104        // svi[128] (edge) or Wc[256] floats (var)
#define SMEM_TOTAL 176128

__device__ __forceinline__ uint32_t smem_u32_of(const void* p) {
    uint32_t a;
    asm("{ .reg .u64 t; cvta.to.shared.u64 t, %1; cvt.u32.u64 %0, t; }" : "=r"(a) : "l"(p));
    return a;
}
__device__ __forceinline__ void ldsm4(uint32_t* r, uint32_t addr) {
    asm volatile("ldmatrix.sync.aligned.m8n8.x4.shared.b16 {%0,%1,%2,%3}, [%4];"
                 : "=r"(r[0]), "=r"(r[1]), "=r"(r[2]), "=r"(r[3]) : "r"(addr));
}
__device__ __forceinline__ void mma16816(float* c, const uint32_t* a, const uint32_t* b) {
    asm volatile("mma.sync.aligned.m16n8k16.row.col.f32.bf16.bf16.f32 "
                 "{%0,%1,%2,%3}, {%4,%5,%6,%7}, {%8,%9}, {%0,%1,%2,%3};"
                 : "+f"(c[0]), "+f"(c[1]), "+f"(c[2]), "+f"(c[3])
                 : "r"(a[0]), "r"(a[1]), "r"(a[2]), "r"(a[3]), "r"(b[0]), "r"(b[1]));
}
__device__ __forceinline__ void cpa16(uint32_t dst, const void* src) {
    asm volatile("cp.async.cg.shared.global [%0], [%1], 16;" :: "r"(dst), "l"(src) : "memory");
}
#define CP_COMMIT() asm volatile("cp.async.commit_group;" ::: "memory")

__device__ __forceinline__ float lsig(float x) {
    return fminf(x, 0.0f) - __logf(1.0f + __expf(-fabsf(x)));
}
// split fp32 pair (a,b) -> bf16x2 hi (a in low 16) and bf16x2 lo
__device__ __forceinline__ void cvt2(float a, float b, uint32_t& h, uint32_t& l) {
    __nv_bfloat16 ah = __float2bfloat16(a), bh = __float2bfloat16(b);
    __nv_bfloat16 al = __float2bfloat16(a - __bfloat162float(ah));
    __nv_bfloat16 bl = __float2bfloat16(b - __bfloat162float(bh));
    h = ((uint32_t)__bfloat16_as_ushort(bh) << 16) | (uint32_t)__bfloat16_as_ushort(ah);
    l = ((uint32_t)__bfloat16_as_ushort(bl) << 16) | (uint32_t)__bfloat16_as_ushort(al);
}

// ---------------- prep: fp32 W[N][Kv] -> bf16 W'[n][2K] hi|lo, zero-padded ----------------
__global__ void prep_w_kernel(const float* __restrict__ src, int which, int N, int Kv, int K) {
    int i = blockIdx.x * 256 + threadIdx.x;
    if (i >= N * K) return;
    __nv_bfloat16* dst = (which == 0) ? g_w1m_p : (which == 1) ? g_w2m_p
                       : (which == 2) ? g_w1a_p : g_w2a_p;
    int n = i / K, k = i % K;
    float v = (k < Kv) ? __ldg(src + (size_t)n * Kv + k) : 0.f;
    __nv_bfloat16 h = __float2bfloat16(v);
    __nv_bfloat16 l = __float2bfloat16(v - __bfloat162float(h));
    dst[(size_t)n * 2 * K + k]     = h;
    dst[(size_t)n * 2 * K + K + k] = l;
}

__global__ void zero_agg_kernel() {
    size_t idx = (size_t)blockIdx.x * blockDim.x + threadIdx.x;
    reinterpret_cast<float4*>(g_agg)[idx] = make_float4(0.f, 0.f, 0.f, 0.f);
}

// ---------------- 3-pass hi/lo GEMM: C[128 x Nrows] += A(smem) x B(global)^T ----------------
// A smem: [128][2K] bf16 stride astr (hi cols 0..K-1, lo K..2K-1)
// B global: W'[n][2K] n-major. Passes: (Ah,Bh),(Al,Bh),(Ah,Bl).
template <int NTILES>   // warp covers NTILES*8 output cols; 4 warp_n cover Nrows
__device__ __forceinline__ void gemm3(
    const __nv_bfloat16* __restrict__ Bg, int K, int NC, int Nrows,
    uint32_t aBase, int astr, uint32_t bBase,
    int wm, int wn, int lane, int tid, float acc[2][NTILES][4])
{
    const int TOT = 3 * NC;
    auto issue = [&](int g, int buf) {
        int pass = g / NC, kc = g % NC;
        int boff = (pass == 2) ? K : 0;
        for (int idx = tid; idx < Nrows * 4; idx += 512) {
            int n = idx >> 2, seg = idx & 3;
            const char* src = (const char*)Bg
                + (((size_t)n * 2 * K) + boff + kc * 32 + seg * 8) * 2;
            cpa16(bBase + buf * 20480 + n * 80 + seg * 16, src);
        }
        CP_COMMIT();
    };

    issue(0, 0);
#pragma unroll 1
    for (int g = 0; g < TOT; g++) {
        int buf = g & 1;
        if (g + 1 < TOT) {
            issue(g + 1, buf ^ 1);
            asm volatile("cp.async.wait_group 1;" ::: "memory");
        } else {
            asm volatile("cp.async.wait_group 0;" ::: "memory");
        }
        __syncthreads();
        int pass = g / NC, kc = g % NC;
        int acol0 = ((pass == 1) ? K : 0) + kc * 32;
#pragma unroll
        for (int ks = 0; ks < 32; ks += 16) {
            uint32_t a[2][4];
#pragma unroll
            for (int mt = 0; mt < 2; mt++) {
                uint32_t ad = aBase
                    + (uint32_t)((wm * 32 + mt * 16 + (lane & 15)) * astr + acol0 + ks) * 2
                    + ((lane >> 4) << 4);
                ldsm4(a[mt], ad);
            }
            uint32_t b[NTILES][2];
#pragma unroll
            for (int p = 0; p < NTILES / 2; p++) {
                int grp = lane >> 3;
                int nrow = wn * (NTILES * 8) + p * 16 + ((grp >> 1) << 3) + (lane & 7);
                int kk = ks + ((grp & 1) << 3);
                uint32_t t[4];
                ldsm4(t, bBase + buf * 20480 + nrow * 80 + kk * 2);
                b[2 * p][0] = t[0]; b[2 * p][1] = t[1];
                b[2 * p + 1][0] = t[2]; b[2 * p + 1][1] = t[3];
            }
#pragma unroll
            for (int mt = 0; mt < 2; mt++)
#pragma unroll
                for (int nt = 0; nt < NTILES; nt++)
                    mma16816(acc[mt][nt], a[mt], b[nt]);
        }
        __syncthreads();
    }
}

// GEMM1 epilogue: acc -> lsig(+bias) -> h1 hi/lo bf16 in A region ([128][520], lo at +256)
__device__ __forceinline__ void epi_h1(float acc[2][8][4], const float* bias,
                                       char* smx, int wm, int wn, int lane) {
#pragma unroll
    for (int mt = 0; mt < 2; mt++)
#pragma unroll
        for (int nt = 0; nt < 8; nt++) {
            int row = wm * 32 + mt * 16 + (lane >> 2);
            int col = wn * 64 + nt * 8 + 2 * (lane & 3);
            uint32_t hh, ll;
            float a0 = lsig(acc[mt][nt][0] + bias[col]);
            float a1 = lsig(acc[mt][nt][1] + bias[col + 1]);
            cvt2(a0, a1, hh, ll);
            *(uint32_t*)(smx + (row * 520 + col) * 2) = hh;
            *(uint32_t*)(smx + (row * 520 + 256 + col) * 2) = ll;
            float a2 = lsig(acc[mt][nt][2] + bias[col]);
            float a3 = lsig(acc[mt][nt][3] + bias[col + 1]);
            cvt2(a2, a3, hh, ll);
            *(uint32_t*)(smx + ((row + 8) * 520 + col) * 2) = hh;
            *(uint32_t*)(smx + ((row + 8) * 520 + 256 + col) * 2) = ll;
        }
}

// ---------------- edge kernel: X -> MLP(145,256,256) -> RED scatter ----------------
__global__ __launch_bounds__(512, 1) void edge_kernel(
    const float* __restrict__ vs, const float* __restrict__ ef,
    const float* __restrict__ sol, const float* __restrict__ b1m,
    const int* __restrict__ vidx, const int* __restrict__ esign)
{
    extern __shared__ char smx[];
    uint32_t sb = smem_u32_of(smx);
    const int tid = threadIdx.x, lane = tid & 31, wid = tid >> 5;
    const int wm = wid & 3, wn = wid >> 2;
    const size_t ebase = (size_t)blockIdx.x * 128;
    float* bias = (float*)(smx + BIAS_OFF);
    int* svi = (int*)(smx + AUX_OFF);

    if (tid < 128) ((float2*)bias)[tid] = ((const float2*)b1m)[tid];

    // ---- stage A = [state|ef|signed|pad] hi/lo into [128][328] bf16 ----
    for (int idx = tid; idx < 128 * 80; idx += 512) {
        int row = idx / 80, p = idx - row * 80, c0 = 2 * p;
        size_t grow = ebase + row;
        bool ok = grow < (size_t)E_N;
        float v0 = 0.f, v1 = 0.f;
        if (ok) {
            if (c0 < 128) { float2 t = __ldg((const float2*)(vs + grow * 128 + c0)); v0 = t.x; v1 = t.y; }
            else if (c0 < 144) { float2 t = __ldg((const float2*)(ef + grow * 16 + (c0 - 128))); v0 = t.x; v1 = t.y; }
            else if (c0 == 144) {
                int vi = __ldg(vidx + grow);
                svi[row] = vi;
                v0 = (float)__ldg(esign + grow) * __ldg(sol + vi);
            }
        } else if (c0 == 144) svi[row] = 0;
        uint32_t hh, ll;
        cvt2(v0, v1, hh, ll);
        *(uint32_t*)(smx + (row * 328 + c0) * 2) = hh;
        *(uint32_t*)(smx + (row * 328 + 160 + c0) * 2) = ll;
    }

    float acc[2][8][4];
#pragma unroll
    for (int i = 0; i < 2; i++)
#pragma unroll
        for (int j = 0; j < 8; j++)
#pragma unroll
            for (int q = 0; q < 4; q++) acc[i][j][q] = 0.f;

    // GEMM1: K=160, NC=5  (A stride 328)
    gemm3<8>(g_w1m_p, 160, 5, 256, sb, 328, sb + B_OFF, wm, wn, lane, tid, acc);
    epi_h1(acc, bias, smx, wm, wn, lane);
#pragma unroll
    for (int i = 0; i < 2; i++)
#pragma unroll
        for (int j = 0; j < 8; j++)
#pragma unroll
            for (int q = 0; q < 4; q++) acc[i][j][q] = 0.f;
    __syncthreads();

    // GEMM2: K=256, NC=8 (A = h1, stride 520)
    gemm3<8>(g_w2m_p, 256, 8, 256, sb, 520, sb + B_OFF, wm, wn, lane, tid, acc);

    // epilogue: lsig -> fp32 h2 [128][260] in A region
    float* h2f = (float*)smx;
#pragma unroll
    for (int mt = 0; mt < 2; mt++)
#pragma unroll
        for (int nt = 0; nt < 8; nt++) {
            int row = wm * 32 + mt * 16 + (lane >> 2);
            int col = wn * 64 + nt * 8 + 2 * (lane & 3);
            h2f[row * 260 + col]     = lsig(acc[mt][nt][0]);
            h2f[row * 260 + col + 1] = lsig(acc[mt][nt][1]);
            h2f[(row + 8) * 260 + col]     = lsig(acc[mt][nt][2]);
            h2f[(row + 8) * 260 + col + 1] = lsig(acc[mt][nt][3]);
        }
    __syncthreads();

    // coalesced vector-RED scatter
    for (int i = tid; i < 128 * 64; i += 512) {
        int row = i >> 6, seg = i & 63;
        if (ebase + row < (size_t)E_N) {
            float4 v = *(float4*)(h2f + row * 260 + seg * 4);
            atomicAdd((float4*)(g_agg + (size_t)svi[row] * 256 + seg * 4), v);
        }
    }
}

// ---------------- var kernel: g_agg -> MLP(256,256,128) -> classifier(128,2) ----------------
__global__ __launch_bounds__(512, 1) void var_kernel(
    const float* __restrict__ b1a, const float* __restrict__ Wc,
    const float* __restrict__ bc, float* __restrict__ out)
{
    extern __shared__ char smx[];
    uint32_t sb = smem_u32_of(smx);
    const int tid = threadIdx.x, lane = tid & 31, wid = tid >> 5;
    const int wm = wid & 3, wn = wid >> 2;
    const size_t vb = (size_t)blockIdx.x * 128;
    float* bias = (float*)(smx + BIAS_OFF);
    float* wc = (float*)(smx + AUX_OFF);

    if (tid < 128) {
        ((float2*)bias)[tid] = ((const float2*)b1a)[tid];
        ((float2*)wc)[tid]   = ((const float2*)Wc)[tid];
    }

    // ---- stage A = g_agg rows hi/lo into [128][520] ----
    for (int idx = tid; idx < 128 * 128; idx += 512) {
        int row = idx >> 7, p = idx & 127, c0 = 2 * p;
        size_t gv = vb + row;
        float2 t = (gv < (size_t)V_N) ? *(const float2*)(g_agg + gv * 256 + c0)
                                      : make_float2(0.f, 0.f);
        uint32_t hh, ll;
        cvt2(t.x, t.y, hh, ll);
        *(uint32_t*)(smx + (row * 520 + c0) * 2) = hh;
        *(uint32_t*)(smx + (row * 520 + 256 + c0) * 2) = ll;
    }

    float acc[2][8][4];
#pragma unroll
    for (int i = 0; i < 2; i++)
#pragma unroll
        for (int j = 0; j < 8; j++)
#pragma unroll
            for (int q = 0; q < 4; q++) acc[i][j][q] = 0.f;

    // GEMM1: K=256, NC=8
    gemm3<8>(g_w1a_p, 256, 8, 256, sb, 520, sb + B_OFF, wm, wn, lane, tid, acc);
    epi_h1(acc, bias, smx, wm, wn, lane);
    __syncthreads();

    // GEMM2: N=128, K=256 (warp tile 32x32)
    float acc2[2][4][4];
#pragma unroll
    for (int i = 0; i < 2; i++)
#pragma unroll
        for (int j = 0; j < 4; j++)
#pragma unroll
            for (int q = 0; q < 4; q++) acc2[i][j][q] = 0.f;
    gemm3<4>(g_w2a_p, 256, 8, 128, sb, 520, sb + B_OFF, wm, wn, lane, tid, acc2);

    // epilogue: lsig -> fp32 h2 [128][132]
    float* h2f = (float*)smx;
#pragma unroll
    for (int mt = 0; mt < 2; mt++)
#pragma unroll
        for (int nt = 0; nt < 4; nt++) {
            int row = wm * 32 + mt * 16 + (lane >> 2);
            int col = wn * 32 + nt * 8 + 2 * (lane & 3);
            h2f[row * 132 + col]     = lsig(acc2[mt][nt][0]);
            h2f[row * 132 + col + 1] = lsig(acc2[mt][nt][1]);
            h2f[(row + 8) * 132 + col]     = lsig(acc2[mt][nt][2]);
            h2f[(row + 8) * 132 + col + 1] = lsig(acc2[mt][nt][3]);
        }
    __syncthreads();

    // classifier: out[row] = Wc @ h2row + bc
    if (tid < 256) {
        int row = tid >> 1, p = tid & 1;
        float s = __ldg(bc + p);
        const float* wcp = wc + p * 128;
        const float* hr = h2f + row * 132;
#pragma unroll 8
        for (int j = 0; j < 128; j++) s = fmaf(hr[j], wcp[j], s);
        size_t gv = vb + row;
        if (gv < (size_t)V_N) out[gv * 2 + p] = s;
    }
}

// ---------------- launch ----------------
extern "C" void kernel_launch(void* const* d_in, const int* in_sizes, int n_in,
                              void* d_out, int out_size)
{
    const float* vs   = (const float*)d_in[0];
    const float* ef   = (const float*)d_in[1];
    const float* sol  = (const float*)d_in[2];
    const float* W1m  = (const float*)d_in[3];
    const float* b1m  = (const float*)d_in[4];
    const float* W2m  = (const float*)d_in[5];
    const float* W1a  = (const float*)d_in[6];
    const float* b1a  = (const float*)d_in[7];
    const float* W2a  = (const float*)d_in[8];
    const float* Wc   = (const float*)d_in[9];
    const float* bc   = (const float*)d_in[10];
    const int*  vidx  = (const int*)d_in[11];
    const int*  esign = (const int*)d_in[12];
    float* out = (float*)d_out;

    cudaFuncSetAttribute(edge_kernel, cudaFuncAttributeMaxDynamicSharedMemorySize, SMEM_TOTAL);
    cudaFuncSetAttribute(var_kernel,  cudaFuncAttributeMaxDynamicSharedMemorySize, SMEM_TOTAL);

    zero_agg_kernel<<<50000, 256>>>();
    prep_w_kernel<<<(256 * 160 + 255) / 256, 256>>>(W1m, 0, 256, 145, 160);
    prep_w_kernel<<<(256 * 256 + 255) / 256, 256>>>(W2m, 1, 256, 256, 256);
    prep_w_kernel<<<(256 * 256 + 255) / 256, 256>>>(W1a, 2, 256, 256, 256);
    prep_w_kernel<<<(128 * 256 + 255) / 256, 256>>>(W2a, 3, 128, 256, 256);
    edge_kernel<<<(E_N + 127) / 128, 512, SMEM_TOTAL>>>(vs, ef, sol, b1m, vidx, esign);
    var_kernel<<<(V_N + 127) / 128, 512, SMEM_TOTAL>>>(b1a, Wc, bc, out);
}

// round 10
// speedup vs baseline: 3.1812x; 1.0176x over previous
#include <cuda_runtime.h>
#include <cuda_bf16.h>
#include <cstdint>
#include <cstddef>

#define E_N 1000000
#define V_N 200000

// ---------------- device scratch (allocation-free rule) ----------------
__device__ __align__(128) float g_agg[(size_t)V_N * 256];
// n-major bf16 weights, hi|lo concatenated along k: W'[n][2K]
__device__ __align__(128) __nv_bfloat16 g_w1m_p[256 * 320];   // K=160 (145 valid)
__device__ __align__(128) __nv_bfloat16 g_w2m_p[256 * 512];   // K=256
__device__ __align__(128) __nv_bfloat16 g_w1a_p[256 * 512];   // K=256
__device__ __align__(128) __nv_bfloat16 g_w2a_p[128 * 512];   // K=256, N=128

// ---------------- smem layout (bytes) ----------------
// A/h1/h2 region: 128 x 520 bf16 = 133120 (also reused as 128 x 260 fp32)
// B ring: 3 stages x [256 rows x stride 56 bf16] = 3 x 28672
#define B_OFF     133120
#define B_STAGE   28672
#define B_STRIDE  56              // bf16 elems; 112 B: conflict-free ldmatrix phases
#define BIAS_OFF  219136          // 256 floats
#define AUX_OFF   220160          // svi[128] (edge) or Wc[256] floats (var)
#define SMEM_TOTAL 221184

__device__ __forceinline__ uint32_t smem_u32_of(const void* p) {
    uint32_t a;
    asm("{ .reg .u64 t; cvta.to.shared.u64 t, %1; cvt.u32.u64 %0, t; }" : "=r"(a) : "l"(p));
    return a;
}
__device__ __forceinline__ void ldsm4(uint32_t* r, uint32_t addr) {
    asm volatile("ldmatrix.sync.aligned.m8n8.x4.shared.b16 {%0,%1,%2,%3}, [%4];"
                 : "=r"(r[0]), "=r"(r[1]), "=r"(r[2]), "=r"(r[3]) : "r"(addr));
}
__device__ __forceinline__ void mma16816(float* c, const uint32_t* a, const uint32_t* b) {
    asm volatile("mma.sync.aligned.m16n8k16.row.col.f32.bf16.bf16.f32 "
                 "{%0,%1,%2,%3}, {%4,%5,%6,%7}, {%8,%9}, {%0,%1,%2,%3};"
                 : "+f"(c[0]), "+f"(c[1]), "+f"(c[2]), "+f"(c[3])
                 : "r"(a[0]), "r"(a[1]), "r"(a[2]), "r"(a[3]), "r"(b[0]), "r"(b[1]));
}
__device__ __forceinline__ void cpa16(uint32_t dst, const void* src) {
    asm volatile("cp.async.cg.shared.global [%0], [%1], 16;" :: "r"(dst), "l"(src) : "memory");
}
#define CP_COMMIT() asm volatile("cp.async.commit_group;" ::: "memory")

__device__ __forceinline__ float lsig(float x) {
    return fminf(x, 0.0f) - __logf(1.0f + __expf(-fabsf(x)));
}
// split fp32 pair (a,b) -> bf16x2 hi (a in low 16) and bf16x2 lo
__device__ __forceinline__ void cvt2(float a, float b, uint32_t& h, uint32_t& l) {
    __nv_bfloat16 ah = __float2bfloat16(a), bh = __float2bfloat16(b);
    __nv_bfloat16 al = __float2bfloat16(a - __bfloat162float(ah));
    __nv_bfloat16 bl = __float2bfloat16(b - __bfloat162float(bh));
    h = ((uint32_t)__bfloat16_as_ushort(bh) << 16) | (uint32_t)__bfloat16_as_ushort(ah);
    l = ((uint32_t)__bfloat16_as_ushort(bl) << 16) | (uint32_t)__bfloat16_as_ushort(al);
}

// ---------------- prep: fp32 W[N][Kv] -> bf16 W'[n][2K] hi|lo, zero-padded ----------------
__global__ void prep_w_kernel(const float* __restrict__ src, int which, int N, int Kv, int K) {
    int i = blockIdx.x * 256 + threadIdx.x;
    if (i >= N * K) return;
    __nv_bfloat16* dst = (which == 0) ? g_w1m_p : (which == 1) ? g_w2m_p
                       : (which == 2) ? g_w1a_p : g_w2a_p;
    int n = i / K, k = i % K;
    float v = (k < Kv) ? __ldg(src + (size_t)n * Kv + k) : 0.f;
    __nv_bfloat16 h = __float2bfloat16(v);
    __nv_bfloat16 l = __float2bfloat16(v - __bfloat162float(h));
    dst[(size_t)n * 2 * K + k]     = h;
    dst[(size_t)n * 2 * K + K + k] = l;
}

__global__ void zero_agg_kernel() {
    size_t idx = (size_t)blockIdx.x * blockDim.x + threadIdx.x;
    reinterpret_cast<float4*>(g_agg)[idx] = make_float4(0.f, 0.f, 0.f, 0.f);
}

// ---------------- 3-pass hi/lo GEMM, 3-stage cp.async ring, 1 sync/iter ----------------
// A smem: [128][2K] bf16 stride astr (hi cols 0..K-1, lo K..2K-1)
// B global: W'[n][2K] n-major. Virtual chunk sequence g=0..3*NC-1:
//   pass 0: Ah x Bh, pass 1: Al x Bh, pass 2: Ah x Bl
template <int NTILES>   // warp covers NTILES*8 output cols; 4 warp_n cover Nrows
__device__ __forceinline__ void gemm3(
    const __nv_bfloat16* __restrict__ Bg, int K, int NC, int Nrows,
    uint32_t aBase, int astr, uint32_t bBase,
    int wm, int wn, int lane, int tid, float acc[2][NTILES][4])
{
    const int TOT = 3 * NC;
    auto issue = [&](int g, int slot) {
        int pass = g / NC, kc = g % NC;
        int boff = (pass == 2) ? K : 0;
        for (int idx = tid; idx < Nrows * 4; idx += 512) {
            int n = idx >> 2, seg = idx & 3;
            const char* src = (const char*)Bg
                + (((size_t)n * 2 * K) + boff + kc * 32 + seg * 8) * 2;
            cpa16(bBase + slot * B_STAGE + n * (B_STRIDE * 2) + seg * 16, src);
        }
        CP_COMMIT();
    };

    issue(0, 0);
    issue(1, 1);
#pragma unroll 1
    for (int g = 0; g < TOT; g++) {
        int slot = g % 3;
        asm volatile("cp.async.wait_group 1;" ::: "memory");   // stage g resident
        __syncthreads();                                       // visibility + ring-slot reuse safety
        if (g + 2 < TOT) issue(g + 2, (g + 2) % 3);            // overwrites slot (g-1): all done with it

        int pass = g / NC, kc = g % NC;
        int acol0 = ((pass == 1) ? K : 0) + kc * 32;
        uint32_t bStage = bBase + slot * B_STAGE;
#pragma unroll
        for (int ks = 0; ks < 32; ks += 16) {
            uint32_t a[2][4];
#pragma unroll
            for (int mt = 0; mt < 2; mt++) {
                uint32_t ad = aBase
                    + (uint32_t)((wm * 32 + mt * 16 + (lane & 15)) * astr + acol0 + ks) * 2
                    + ((lane >> 4) << 4);
                ldsm4(a[mt], ad);
            }
            uint32_t b[NTILES][2];
#pragma unroll
            for (int p = 0; p < NTILES / 2; p++) {
                int grp = lane >> 3;
                int nrow = wn * (NTILES * 8) + p * 16 + ((grp >> 1) << 3) + (lane & 7);
                int kk = ks + ((grp & 1) << 3);
                uint32_t t[4];
                ldsm4(t, bStage + nrow * (B_STRIDE * 2) + kk * 2);
                b[2 * p][0] = t[0]; b[2 * p][1] = t[1];
                b[2 * p + 1][0] = t[2]; b[2 * p + 1][1] = t[3];
            }
#pragma unroll
            for (int mt = 0; mt < 2; mt++)
#pragma unroll
                for (int nt = 0; nt < NTILES; nt++)
                    mma16816(acc[mt][nt], a[mt], b[nt]);
        }
    }
    __syncthreads();   // callers reuse A region right after
}

// GEMM1 epilogue: acc -> lsig(+bias) -> h1 hi/lo bf16 in A region ([128][520], lo at +256)
__device__ __forceinline__ void epi_h1(float acc[2][8][4], const float* bias,
                                       char* smx, int wm, int wn, int lane) {
#pragma unroll
    for (int mt = 0; mt < 2; mt++)
#pragma unroll
        for (int nt = 0; nt < 8; nt++) {
            int row = wm * 32 + mt * 16 + (lane >> 2);
            int col = wn * 64 + nt * 8 + 2 * (lane & 3);
            uint32_t hh, ll;
            float a0 = lsig(acc[mt][nt][0] + bias[col]);
            float a1 = lsig(acc[mt][nt][1] + bias[col + 1]);
            cvt2(a0, a1, hh, ll);
            *(uint32_t*)(smx + (row * 520 + col) * 2) = hh;
            *(uint32_t*)(smx + (row * 520 + 256 + col) * 2) = ll;
            float a2 = lsig(acc[mt][nt][2] + bias[col]);
            float a3 = lsig(acc[mt][nt][3] + bias[col + 1]);
            cvt2(a2, a3, hh, ll);
            *(uint32_t*)(smx + ((row + 8) * 520 + col) * 2) = hh;
            *(uint32_t*)(smx + ((row + 8) * 520 + 256 + col) * 2) = ll;
        }
}

// ---------------- edge kernel: X -> MLP(145,256,256) -> RED scatter ----------------
__global__ __launch_bounds__(512, 1) void edge_kernel(
    const float* __restrict__ vs, const float* __restrict__ ef,
    const float* __restrict__ sol, const float* __restrict__ b1m,
    const int* __restrict__ vidx, const int* __restrict__ esign)
{
    extern __shared__ char smx[];
    uint32_t sb = smem_u32_of(smx);
    const int tid = threadIdx.x, lane = tid & 31, wid = tid >> 5;
    const int wm = wid & 3, wn = wid >> 2;
    const size_t ebase = (size_t)blockIdx.x * 128;
    float* bias = (float*)(smx + BIAS_OFF);
    int* svi = (int*)(smx + AUX_OFF);

    if (tid < 128) ((float2*)bias)[tid] = ((const float2*)b1m)[tid];

    // ---- stage A = [state|ef|signed|pad] hi/lo into [128][328] bf16 ----
    for (int idx = tid; idx < 128 * 80; idx += 512) {
        int row = idx / 80, p = idx - row * 80, c0 = 2 * p;
        size_t grow = ebase + row;
        bool ok = grow < (size_t)E_N;
        float v0 = 0.f, v1 = 0.f;
        if (ok) {
            if (c0 < 128) { float2 t = __ldg((const float2*)(vs + grow * 128 + c0)); v0 = t.x; v1 = t.y; }
            else if (c0 < 144) { float2 t = __ldg((const float2*)(ef + grow * 16 + (c0 - 128))); v0 = t.x; v1 = t.y; }
            else if (c0 == 144) {
                int vi = __ldg(vidx + grow);
                svi[row] = vi;
                v0 = (float)__ldg(esign + grow) * __ldg(sol + vi);
            }
        } else if (c0 == 144) svi[row] = 0;
        uint32_t hh, ll;
        cvt2(v0, v1, hh, ll);
        *(uint32_t*)(smx + (row * 328 + c0) * 2) = hh;
        *(uint32_t*)(smx + (row * 328 + 160 + c0) * 2) = ll;
    }

    float acc[2][8][4];
#pragma unroll
    for (int i = 0; i < 2; i++)
#pragma unroll
        for (int j = 0; j < 8; j++)
#pragma unroll
            for (int q = 0; q < 4; q++) acc[i][j][q] = 0.f;

    // GEMM1: K=160, NC=5  (A stride 328)
    gemm3<8>(g_w1m_p, 160, 5, 256, sb, 328, sb + B_OFF, wm, wn, lane, tid, acc);
    epi_h1(acc, bias, smx, wm, wn, lane);
#pragma unroll
    for (int i = 0; i < 2; i++)
#pragma unroll
        for (int j = 0; j < 8; j++)
#pragma unroll
            for (int q = 0; q < 4; q++) acc[i][j][q] = 0.f;

    // GEMM2: K=256, NC=8 (A = h1, stride 520); internal first sync covers epi writes
    gemm3<8>(g_w2m_p, 256, 8, 256, sb, 520, sb + B_OFF, wm, wn, lane, tid, acc);

    // epilogue: lsig -> fp32 h2 [128][260] in A region
    float* h2f = (float*)smx;
#pragma unroll
    for (int mt = 0; mt < 2; mt++)
#pragma unroll
        for (int nt = 0; nt < 8; nt++) {
            int row = wm * 32 + mt * 16 + (lane >> 2);
            int col = wn * 64 + nt * 8 + 2 * (lane & 3);
            h2f[row * 260 + col]     = lsig(acc[mt][nt][0]);
            h2f[row * 260 + col + 1] = lsig(acc[mt][nt][1]);
            h2f[(row + 8) * 260 + col]     = lsig(acc[mt][nt][2]);
            h2f[(row + 8) * 260 + col + 1] = lsig(acc[mt][nt][3]);
        }
    __syncthreads();

    // coalesced vector-RED scatter
    for (int i = tid; i < 128 * 64; i += 512) {
        int row = i >> 6, seg = i & 63;
        if (ebase + row < (size_t)E_N) {
            float4 v = *(float4*)(h2f + row * 260 + seg * 4);
            atomicAdd((float4*)(g_agg + (size_t)svi[row] * 256 + seg * 4), v);
        }
    }
}

// ---------------- var kernel: g_agg -> MLP(256,256,128) -> classifier(128,2) ----------------
__global__ __launch_bounds__(512, 1) void var_kernel(
    const float* __restrict__ b1a, const float* __restrict__ Wc,
    const float* __restrict__ bc, float* __restrict__ out)
{
    extern __shared__ char smx[];
    uint32_t sb = smem_u32_of(smx);
    const int tid = threadIdx.x, lane = tid & 31, wid = tid >> 5;
    const int wm = wid & 3, wn = wid >> 2;
    const size_t vb = (size_t)blockIdx.x * 128;
    float* bias = (float*)(smx + BIAS_OFF);
    float* wc = (float*)(smx + AUX_OFF);

    if (tid < 128) {
        ((float2*)bias)[tid] = ((const float2*)b1a)[tid];
        ((float2*)wc)[tid]   = ((const float2*)Wc)[tid];
    }

    // ---- stage A = g_agg rows hi/lo into [128][520] ----
    for (int idx = tid; idx < 128 * 128; idx += 512) {
        int row = idx >> 7, p = idx & 127, c0 = 2 * p;
        size_t gv = vb + row;
        float2 t = (gv < (size_t)V_N) ? *(const float2*)(g_agg + gv * 256 + c0)
                                      : make_float2(0.f, 0.f);
        uint32_t hh, ll;
        cvt2(t.x, t.y, hh, ll);
        *(uint32_t*)(smx + (row * 520 + c0) * 2) = hh;
        *(uint32_t*)(smx + (row * 520 + 256 + c0) * 2) = ll;
    }

    float acc[2][8][4];
#pragma unroll
    for (int i = 0; i < 2; i++)
#pragma unroll
        for (int j = 0; j < 8; j++)
#pragma unroll
            for (int q = 0; q < 4; q++) acc[i][j][q] = 0.f;

    // GEMM1: K=256, NC=8
    gemm3<8>(g_w1a_p, 256, 8, 256, sb, 520, sb + B_OFF, wm, wn, lane, tid, acc);
    epi_h1(acc, bias, smx, wm, wn, lane);

    // GEMM2: N=128, K=256 (warp tile 32x32)
    float acc2[2][4][4];
#pragma unroll
    for (int i = 0; i < 2; i++)
#pragma unroll
        for (int j = 0; j < 4; j++)
#pragma unroll
            for (int q = 0; q < 4; q++) acc2[i][j][q] = 0.f;
    gemm3<4>(g_w2a_p, 256, 8, 128, sb, 520, sb + B_OFF, wm, wn, lane, tid, acc2);

    // epilogue: lsig -> fp32 h2 [128][132]
    float* h2f = (float*)smx;
#pragma unroll
    for (int mt = 0; mt < 2; mt++)
#pragma unroll
        for (int nt = 0; nt < 4; nt++) {
            int row = wm * 32 + mt * 16 + (lane >> 2);
            int col = wn * 32 + nt * 8 + 2 * (lane & 3);
            h2f[row * 132 + col]     = lsig(acc2[mt][nt][0]);
            h2f[row * 132 + col + 1] = lsig(acc2[mt][nt][1]);
            h2f[(row + 8) * 132 + col]     = lsig(acc2[mt][nt][2]);
            h2f[(row + 8) * 132 + col + 1] = lsig(acc2[mt][nt][3]);
        }
    __syncthreads();

    // classifier: out[row] = Wc @ h2row + bc
    if (tid < 256) {
        int row = tid >> 1, p = tid & 1;
        float s = __ldg(bc + p);
        const float* wcp = wc + p * 128;
        const float* hr = h2f + row * 132;
#pragma unroll 8
        for (int j = 0; j < 128; j++) s = fmaf(hr[j], wcp[j], s);
        size_t gv = vb + row;
        if (gv < (size_t)V_N) out[gv * 2 + p] = s;
    }
}

// ---------------- launch ----------------
extern "C" void kernel_launch(void* const* d_in, const int* in_sizes, int n_in,
                              void* d_out, int out_size)
{
    const float* vs   = (const float*)d_in[0];
    const float* ef   = (const float*)d_in[1];
    const float* sol  = (const float*)d_in[2];
    const float* W1m  = (const float*)d_in[3];
    const float* b1m  = (const float*)d_in[4];
    const float* W2m  = (const float*)d_in[5];
    const float* W1a  = (const float*)d_in[6];
    const float* b1a  = (const float*)d_in[7];
    const float* W2a  = (const float*)d_in[8];
    const float* Wc   = (const float*)d_in[9];
    const float* bc   = (const float*)d_in[10];
    const int*  vidx  = (const int*)d_in[11];
    const int*  esign = (const int*)d_in[12];
    float* out = (float*)d_out;

    cudaFuncSetAttribute(edge_kernel, cudaFuncAttributeMaxDynamicSharedMemorySize, SMEM_TOTAL);
    cudaFuncSetAttribute(var_kernel,  cudaFuncAttributeMaxDynamicSharedMemorySize, SMEM_TOTAL);

    // prep first, zero second: keeps deps intact and puts edge_kernel at ncu's -s 5 slot
    prep_w_kernel<<<(256 * 160 + 255) / 256, 256>>>(W1m, 0, 256, 145, 160);
    prep_w_kernel<<<(256 * 256 + 255) / 256, 256>>>(W2m, 1, 256, 256, 256);
    prep_w_kernel<<<(256 * 256 + 255) / 256, 256>>>(W1a, 2, 256, 256, 256);
    prep_w_kernel<<<(128 * 256 + 255) / 256, 256>>>(W2a, 3, 128, 256, 256);
    zero_agg_kernel<<<50000, 256>>>();
    edge_kernel<<<(E_N + 127) / 128, 512, SMEM_TOTAL>>>(vs, ef, sol, b1m, vidx, esign);
    var_kernel<<<(V_N + 127) / 128, 512, SMEM_TOTAL>>>(b1a, Wc, bc, out);
}